// round 14
// baseline (speedup 1.0000x reference)
#include <cuda_runtime.h>

#define BB 8
#define HH 256
#define KK 256
#define EE 128

__device__ float g_delta[BB * HH * KK];   // masked exp(u)  2 MB
__device__ float g_sum[BB * EE];          // atomic H-sums
__device__ float g_cnt[BB * EE];          // atomic nonzero counts
__device__ int   g_arrive[BB];            // agg CTA arrival counters

// ---------------- Kernel 1: fused gather+transpose+scores ----------------
// grid (4 ktiles of 64, 8 htiles of 32, BB), 128 threads, ~98 KB dyn smem.
// Stage rows coalesced -> padded buffer -> smem transpose -> reg-blocked GEMM.
__global__ __launch_bounds__(128)
void kvmem_scores(const float* __restrict__ hidden,
                  const float* __restrict__ key_emb,
                  const int*   __restrict__ key_seq,
                  const int*   __restrict__ mask)
{
    extern __shared__ float dyn[];
    float*  s_buf = dyn;                                // [96][129]  49.5 KB
    float4* s_key = (float4*)(dyn + 96 * 129);          // [EE][16]   32 KB
    float4* s_hid = s_key + EE * 16;                    // [EE][8]    16 KB

    const int kt = blockIdx.x;
    const int ht = blockIdx.y;
    const int b  = blockIdx.z;
    const int k0 = kt * 64;
    const int h0 = ht * 32;
    const int t  = threadIdx.x;
    const int tx = t & 15;
    const int ty = t >> 4;

    if (kt == 0 && ht == 0) {            // zero accumulators for this b
        g_sum[b * EE + t] = 0.0f;
        g_cnt[b * EE + t] = 0.0f;
        if (t == 0) g_arrive[b] = 0;
    }

    // stage 64 gathered key rows (r<64) + 32 hidden rows (r>=64), coalesced
    for (int i = t; i < 96 * 32; i += 128) {
        int r  = i >> 5;
        int e4 = i & 31;
        float4 v;
        if (r < 64) {
            int row = key_seq[b * KK + k0 + r];
            v = ((const float4*)(key_emb + (size_t)row * EE))[e4];
        } else {
            v = ((const float4*)(hidden + ((size_t)b * HH + h0 + (r - 64)) * EE))[e4];
        }
        s_buf[r * 129 + 4 * e4 + 0] = v.x;
        s_buf[r * 129 + 4 * e4 + 1] = v.y;
        s_buf[r * 129 + 4 * e4 + 2] = v.z;
        s_buf[r * 129 + 4 * e4 + 3] = v.w;
    }
    __syncthreads();

    // transpose into compute layouts
    for (int i = t; i < EE * 16; i += 128) {
        int e  = i >> 4;
        int k4 = i & 15;
        float4 v;
        v.x = s_buf[(4 * k4 + 0) * 129 + e];
        v.y = s_buf[(4 * k4 + 1) * 129 + e];
        v.z = s_buf[(4 * k4 + 2) * 129 + e];
        v.w = s_buf[(4 * k4 + 3) * 129 + e];
        s_key[i] = v;
    }
    for (int i = t; i < EE * 8; i += 128) {
        int e  = i >> 3;
        int h4 = i & 7;
        float4 v;
        v.x = s_buf[(64 + 4 * h4 + 0) * 129 + e];
        v.y = s_buf[(64 + 4 * h4 + 1) * 129 + e];
        v.z = s_buf[(64 + 4 * h4 + 2) * 129 + e];
        v.w = s_buf[(64 + 4 * h4 + 3) * 129 + e];
        s_hid[i] = v;
    }
    __syncthreads();

    float a00=0,a01=0,a02=0,a03=0, a10=0,a11=0,a12=0,a13=0;
    float a20=0,a21=0,a22=0,a23=0, a30=0,a31=0,a32=0,a33=0;

    #pragma unroll 4
    for (int e = 0; e < EE; e++) {
        float4 hv = s_hid[e * 8 + ty];    // near-broadcast
        float4 kv = s_key[e * 16 + tx];   // conflict-free
        a00 = fmaf(hv.x, kv.x, a00); a01 = fmaf(hv.x, kv.y, a01);
        a02 = fmaf(hv.x, kv.z, a02); a03 = fmaf(hv.x, kv.w, a03);
        a10 = fmaf(hv.y, kv.x, a10); a11 = fmaf(hv.y, kv.y, a11);
        a12 = fmaf(hv.y, kv.z, a12); a13 = fmaf(hv.y, kv.w, a13);
        a20 = fmaf(hv.z, kv.x, a20); a21 = fmaf(hv.z, kv.y, a21);
        a22 = fmaf(hv.z, kv.z, a22); a23 = fmaf(hv.z, kv.w, a23);
        a30 = fmaf(hv.w, kv.x, a30); a31 = fmaf(hv.w, kv.y, a31);
        a32 = fmaf(hv.w, kv.z, a32); a33 = fmaf(hv.w, kv.w, a33);
    }

    const float sc = 0.08838834764831845f;   // 1/sqrt(128)
    float r0c[4] = {a00,a01,a02,a03}, r1c[4] = {a10,a11,a12,a13};
    float r2c[4] = {a20,a21,a22,a23}, r3c[4] = {a30,a31,a32,a33};
    float* rows[4] = {r0c, r1c, r2c, r3c};

    #pragma unroll
    for (int jh = 0; jh < 4; jh++) {
        int h = h0 + ty * 4 + jh;
        size_t base = ((size_t)b * HH + h) * KK + k0 + tx * 4;
        int4 m = *((const int4*)(mask + base));
        float4 ov;
        ov.x = m.x ? expf(rows[jh][0] * sc) : 0.0f;
        ov.y = m.y ? expf(rows[jh][1] * sc) : 0.0f;
        ov.z = m.z ? expf(rows[jh][2] * sc) : 0.0f;
        ov.w = m.w ? expf(rows[jh][3] * sc) : 0.0f;
        *((float4*)(g_delta + base)) = ov;
    }
}

// ---------------- Kernel 2: normalize + aggregation + atomic H-reduce + final ----------------
// grid (HH, BB) = 2048 CTAs, 128 threads; last CTA per b writes the output.
__global__ __launch_bounds__(128)
void kvmem_agg(const float* __restrict__ value_emb,
               const int*   __restrict__ value_seq,
               float* __restrict__ out)
{
    const int h   = blockIdx.x;
    const int b   = blockIdx.y;
    const int t   = threadIdx.x;
    const int w   = t >> 5;
    const int lid = t & 31;
    const int base = (b * HH + h) * KK;

    __shared__ float s_d[KK];
    __shared__ int   s_vidx[KK];
    __shared__ float s_pc[KK];
    __shared__ int   s_vl[KK];
    __shared__ float s_red[4];
    __shared__ int   s_cnt[8];
    __shared__ int   s_basec[8];
    __shared__ float s_invv;
    __shared__ int   s_n;
    __shared__ int   s_last;

    float part = 0.f;
    #pragma unroll
    for (int k = t; k < KK; k += 128) {
        float d = g_delta[base + k];          // already masked
        s_d[k] = d;
        s_vidx[k] = value_seq[base + k];
        part += d;
    }
    #pragma unroll
    for (int m = 16; m > 0; m >>= 1)
        part += __shfl_xor_sync(0xffffffffu, part, m);
    if (lid == 0) s_red[w] = part;
    __syncthreads();
    if (t == 0)
        s_invv = 1.0f / (s_red[0] + s_red[1] + s_red[2] + s_red[3] + 1e-10f);
    __syncthreads();
    const float inv = s_invv;

    unsigned bal[2];
    #pragma unroll
    for (int c2 = 0; c2 < 2; c2++) {
        int c = 2 * w + c2;
        float d = s_d[c * 32 + lid];
        bal[c2] = __ballot_sync(0xffffffffu, d > 0.f);
        if (lid == 0) s_cnt[c] = __popc(bal[c2]);
    }
    __syncthreads();
    if (t == 0) {
        int run = 0;
        #pragma unroll
        for (int c = 0; c < 8; c++) { s_basec[c] = run; run += s_cnt[c]; }
        s_n = run;
    }
    __syncthreads();
    #pragma unroll
    for (int c2 = 0; c2 < 2; c2++) {
        int c = 2 * w + c2;
        int k = c * 32 + lid;
        float d = s_d[k];
        if (d > 0.f) {
            int pos = s_basec[c] + __popc(bal[c2] & ((1u << lid) - 1u));
            s_pc[pos] = d * inv;
            s_vl[pos] = s_vidx[k];
        }
    }
    __syncthreads();

    const int n = s_n;
    float acc = 0.f;
    int i = 0;
    for (; i + 8 <= n; i += 8) {
        #pragma unroll
        for (int j = 0; j < 8; j++)
            acc = fmaf(s_pc[i + j],
                       __ldg(value_emb + (size_t)s_vl[i + j] * EE + t), acc);
    }
    for (; i < n; i++)
        acc = fmaf(s_pc[i], __ldg(value_emb + (size_t)s_vl[i] * EE + t), acc);

    // fused H-reduction via global atomics (cnt adds are exact)
    atomicAdd(&g_sum[b * EE + t], acc);
    if (acc != 0.0f)
        atomicAdd(&g_cnt[b * EE + t], 1.0f);

    // last CTA of this b computes the output
    __threadfence();
    if (t == 0) {
        int a = atomicAdd(&g_arrive[b], 1);
        s_last = (a == HH - 1) ? 1 : 0;
    }
    __syncthreads();
    if (s_last) {
        __threadfence();
        float s = __ldcg(&g_sum[b * EE + t]);   // L1-bypass: see peers' atomics
        float c = __ldcg(&g_cnt[b * EE + t]);
        out[b * EE + t] = s / c;                // reference adds no epsilon here
    }
}

extern "C" void kernel_launch(void* const* d_in, const int* in_sizes, int n_in,
                              void* d_out, int out_size)
{
    const float* hidden    = (const float*)d_in[0];
    const float* key_emb   = (const float*)d_in[1];
    const float* value_emb = (const float*)d_in[2];
    const int*   key_seq   = (const int*)d_in[3];
    const int*   value_seq = (const int*)d_in[4];
    const int*   mask      = (const int*)d_in[5];
    float* out = (float*)d_out;

    const int scores_smem = (96 * 129 + EE * 16 * 4 + EE * 8 * 4) * 4;  // 98688 B
    static int attr_set = 0;
    if (!attr_set) {
        cudaFuncSetAttribute(kvmem_scores,
                             cudaFuncAttributeMaxDynamicSharedMemorySize, scores_smem);
        attr_set = 1;
    }

    kvmem_scores<<<dim3(4, 8, BB), 128, scores_smem>>>(hidden, key_emb, key_seq, mask);
    kvmem_agg<<<dim3(HH, BB), 128>>>(value_emb, value_seq, out);
}